// round 15
// baseline (speedup 1.0000x reference)
#include <cuda_runtime.h>
#include <cuda_bf16.h>
#include <cuda_fp16.h>

#define H     128
#define BATCH 8
#define TQ    512
#define TK    512

// Device scratch (allocation-free rule: __device__ globals)
__device__ __align__(16) __half2 g_kph[BATCH * (H/2) * TK];  // [b][h/2][k] packed h-pairs
__device__ __align__(16) float   g_WaT[H * H];               // Wa transposed: WaT[k][h]

__device__ __forceinline__ __half2 tanh2(__half2 x) {
    unsigned xi = *(unsigned*)&x, yi;
    asm("tanh.approx.f16x2 %0, %1;" : "=r"(yi) : "r"(xi));
    return *(__half2*)&yi;
}

// ---------------------------------------------------------------------------
// Kernel 1: prep (PDL primary).
//   z==0: k-projection with k-split: 256 threads = (h, k-half), 16 chains
//         each over 64 k-terms; partials merged via smem.
//   z==1: Wa transpose into g_WaT (b==0 blocks only).
// grid = (32, B, 2), block = 256
// ---------------------------------------------------------------------------
__global__ void __launch_bounds__(256) prep_kernel(
    const float* __restrict__ keys,
    const float* __restrict__ Ua_w, const float* __restrict__ Ua_b,
    const float* __restrict__ Wa_w)
{
#if __CUDA_ARCH__ >= 900
    cudaTriggerProgrammaticLaunchCompletion();   // let score launch early
#endif
    const int tile = blockIdx.x;   // 32 tiles of 16 rows
    const int b    = blockIdx.y;

    if (blockIdx.z == 1) {
        if (b != 0) return;
        const int r0 = tile * 4;
        #pragma unroll
        for (int i = threadIdx.x; i < 4 * H; i += 256) {
            int r = i >> 7, c = i & 127;
            g_WaT[(size_t)c * H + r0 + r] = Wa_w[(size_t)(r0 + r) * H + c];
        }
        return;
    }

    const int t0 = tile * 16;
    __shared__ __align__(16) float xs[16][H];    // 8 KB input rows
    __shared__ float part[H][16];                // 8 KB k-half partials
    __shared__ float sh[H][16];                  // 8 KB h-pair packing

    const float4* xsrc = (const float4*)(keys + (size_t)(b * 512 + t0) * H);
    #pragma unroll
    for (int i = threadIdx.x; i < 16 * H / 4; i += 256)
        ((float4*)xs)[i] = xsrc[i];
    __syncthreads();

    const int h  = threadIdx.x & 127;   // output column
    const int kh = threadIdx.x >> 7;    // k-half: k in [64*kh, 64*kh+64)

    float acc[16];
    const float init = (kh == 0) ? Ua_b[h] : 0.f;
    #pragma unroll
    for (int t = 0; t < 16; t++) acc[t] = init;

    const float4* Wrow = (const float4*)(Ua_w + (size_t)h * H) + kh * 16;
    #pragma unroll 8
    for (int i = 0; i < 16; i++) {               // 64 k-terms (16 float4)
        float4 w4 = Wrow[i];
        #pragma unroll
        for (int t = 0; t < 16; t++) {
            float4 xv = ((const float4*)xs[t])[kh * 16 + i];
            acc[t] = fmaf(xv.x, w4.x, fmaf(xv.y, w4.y, fmaf(xv.z, w4.z, fmaf(xv.w, w4.w, acc[t]))));
        }
    }

    if (kh == 1) {
        #pragma unroll
        for (int t = 0; t < 16; t++) part[h][t] = acc[t];
    }
    __syncthreads();
    if (kh == 0) {
        #pragma unroll
        for (int t = 0; t < 16; t++) sh[h][t] = acc[t] + part[h][t];
    }
    __syncthreads();

    __half2* dst = g_kph + (size_t)b * (H/2) * TK + t0;
    #pragma unroll
    for (int r = 0; r < 4; r++) {
        int idx = threadIdx.x + 256 * r;   // 0..1023
        int t   = idx & 15;
        int j   = idx >> 4;                // h-pair 0..63
        dst[(size_t)j * TK + t] = __floats2half2_rn(sh[2*j][t], sh[2*j+1][t]);
    }
}

// ---------------------------------------------------------------------------
// Kernel 2: FUSED q-projection + scores + softmax + context (PDL secondary).
// Launches while prep drains; cudaGridDependencySynchronize (after input-only
// qs staging) gates all g_WaT/g_kph reads. Hot loop: round-13 MUFU-floor form.
// grid (TQ/4, B), block 128 (4 warps, 1 q/warp).
// ---------------------------------------------------------------------------
__global__ void __launch_bounds__(128) score_kernel(
    const float* __restrict__ queries,
    const float* __restrict__ keys,
    const float* __restrict__ Wa_b,
    const float* __restrict__ Va_w,
    float* __restrict__ ctx_out,   // (B, TQ, H)
    float* __restrict__ w_out)     // (B, TQ, TK)
{
    __shared__ __align__(16) float  qs[4][H];    // 2 KB raw query rows
    __shared__ __align__(8)  float2 qm[4][H/2];  // 4 KB {q2 bits, va2 bits}
    __shared__ float wsm[4][TK];                 // 8 KB softmax weights

    const int b    = blockIdx.y;
    const int wid  = threadIdx.x >> 5;
    const int lane = threadIdx.x & 31;
    const int q    = blockIdx.x * 4 + wid;

    ((float4*)qs)[threadIdx.x] =
        ((const float4*)(queries + (size_t)(b * TQ + blockIdx.x * 4) * H))[threadIdx.x];
    __syncthreads();

#if __CUDA_ARCH__ >= 900
    cudaGridDependencySynchronize();   // prep done: g_WaT + g_kph visible
#endif

    // ---- Fused q-projection: qp[4lane..4lane+3] = q-row @ Wa^T + b ----
    float4 acc = ((const float4*)Wa_b)[lane];
    {
        const float*  qrow = qs[wid];
        const float4* WT   = (const float4*)g_WaT + lane;   // WaT[k][4lane..+3]
        #pragma unroll 8
        for (int k = 0; k < H; k++) {
            float  xk = qrow[k];        // broadcast LDS
            float4 wv = WT[k * 32];     // coalesced LDG.128, L1-hot
            acc.x = fmaf(xk, wv.x, acc.x);
            acc.y = fmaf(xk, wv.y, acc.y);
            acc.z = fmaf(xk, wv.z, acc.z);
            acc.w = fmaf(xk, wv.w, acc.w);
        }
    }
    {
        __half2 q2a = __floats2half2_rn(acc.x, acc.y);
        __half2 q2b = __floats2half2_rn(acc.z, acc.w);
        float4  vv  = ((const float4*)Va_w)[lane];
        __half2 va0 = __floats2half2_rn(vv.x, vv.y);
        __half2 va1 = __floats2half2_rn(vv.z, vv.w);
        qm[wid][2*lane]   = make_float2(__uint_as_float(*(unsigned*)&q2a),
                                        __uint_as_float(*(unsigned*)&va0));
        qm[wid][2*lane+1] = make_float2(__uint_as_float(*(unsigned*)&q2b),
                                        __uint_as_float(*(unsigned*)&va1));
    }
    __syncwarp();

    // ---- Score hot loop (MUFU floor): lane owns keys 64t + 2lane + e ----
    float a[16];
    #pragma unroll
    for (int i = 0; i < 16; i++) a[i] = 0.f;

    const uint2* kb2 = (const uint2*)(g_kph + (size_t)b * (H/2) * TK) + lane;

    #pragma unroll 1
    for (int jb = 0; jb < 8; jb++) {           // 8 blocks of 8 h-pairs
        __half2 acc2[16];
        #pragma unroll
        for (int i = 0; i < 16; i++) acc2[i] = __half2half2(__float2half(0.f));

        #pragma unroll
        for (int j2 = 0; j2 < 8; j2++) {
            int j = jb * 8 + j2;
            float2 meta = qm[wid][j];          // broadcast LDS.64
            unsigned qb2b = __float_as_uint(meta.x);
            unsigned vb2b = __float_as_uint(meta.y);
            __half2 q2  = *(__half2*)&qb2b;
            __half2 va2 = *(__half2*)&vb2b;

            const uint2* kr = kb2 + j * (TK / 2);
            uint2 kk[8];
            #pragma unroll
            for (int t = 0; t < 8; t++) kk[t] = kr[t * 32];   // MLP=8 LDG.64
            #pragma unroll
            for (int t = 0; t < 8; t++) {
                __half2 k0 = *(__half2*)&kk[t].x;
                __half2 k1 = *(__half2*)&kk[t].y;
                acc2[2*t]   = __hfma2(va2, tanh2(__hadd2(q2, k0)), acc2[2*t]);
                acc2[2*t+1] = __hfma2(va2, tanh2(__hadd2(q2, k1)), acc2[2*t+1]);
            }
        }
        #pragma unroll
        for (int i = 0; i < 16; i++) {
            float2 f = __half22float2(acc2[i]);
            a[i] += f.x + f.y;                 // fold even/odd-h partial sums
        }
    }

    // ---- softmax in registers ----
    float m = a[0];
    #pragma unroll
    for (int i = 1; i < 16; i++) m = fmaxf(m, a[i]);
    #pragma unroll
    for (int o = 16; o > 0; o >>= 1)
        m = fmaxf(m, __shfl_xor_sync(0xffffffffu, m, o));

    float s = 0.f;
    #pragma unroll
    for (int i = 0; i < 16; i++) { a[i] = __expf(a[i] - m); s += a[i]; }
    #pragma unroll
    for (int o = 16; o > 0; o >>= 1)
        s += __shfl_xor_sync(0xffffffffu, s, o);

    const float inv = __fdividef(1.f, s);
    float* wrow = w_out + (size_t)(b * TQ + q) * TK;
    #pragma unroll
    for (int t = 0; t < 8; t++) {
        float2 wp = make_float2(a[2*t] * inv, a[2*t+1] * inv);
        int off = 64 * t + 2 * lane;
        *(float2*)(wrow + off)      = wp;      // required output (coalesced STG.64)
        *(float2*)(&wsm[wid][off])  = wp;      // for fused ctx broadcast reads
    }
    __syncwarp();

    // ---- Fused context: ctx[q][h] = sum_k w[k] * keys[k][h] ----
    float4 cacc = make_float4(0.f, 0.f, 0.f, 0.f);
    const float4* kb = (const float4*)(keys + (size_t)b * TK * H) + lane;
    const float* w0 = wsm[wid];
    #pragma unroll 8
    for (int key = 0; key < TK; key++) {
        float4 kv = kb[key * (H / 4)];         // coalesced LDG.128, L2-hot
        float  wa = w0[key];                   // broadcast LDS
        cacc.x = fmaf(wa, kv.x, cacc.x);
        cacc.y = fmaf(wa, kv.y, cacc.y);
        cacc.z = fmaf(wa, kv.z, cacc.z);
        cacc.w = fmaf(wa, kv.w, cacc.w);
    }
    ((float4*)(ctx_out + (size_t)(b * TQ + q) * H))[lane] = cacc;
}

// ---------------------------------------------------------------------------
extern "C" void kernel_launch(void* const* d_in, const int* in_sizes, int n_in,
                              void* d_out, int out_size)
{
    const float* queries = (const float*)d_in[0];
    const float* keys    = (const float*)d_in[1];
    const float* Wa_w    = (const float*)d_in[2];
    const float* Wa_b    = (const float*)d_in[3];
    const float* Ua_w    = (const float*)d_in[4];
    const float* Ua_b    = (const float*)d_in[5];
    const float* Va_w    = (const float*)d_in[6];
    // Va bias (d_in[7]) cancels in softmax -> unused.

    float* ctx_out = (float*)d_out;                     // (B, TQ, H)
    float* w_out   = ctx_out + BATCH * TQ * H;          // (B, TQ, TK)

    // 1) prep: k-projection (k-split) + Wa transpose, PDL primary.
    dim3 g1(32, BATCH, 2);
    prep_kernel<<<g1, 256>>>(keys, Ua_w, Ua_b, Wa_w);

    // 2) fused score kernel as PDL secondary: launches while prep runs;
    //    grid sync (after input-only staging) gates g_WaT/g_kph reads.
    cudaLaunchConfig_t cfg = {};
    cfg.gridDim  = dim3(TQ / 4, BATCH);
    cfg.blockDim = dim3(128);
    cfg.dynamicSmemBytes = 0;
    cfg.stream = 0;
    cudaLaunchAttribute attrs[1];
    attrs[0].id = cudaLaunchAttributeProgrammaticStreamSerialization;
    attrs[0].val.programmaticStreamSerializationAllowed = 1;
    cfg.attrs = attrs;
    cfg.numAttrs = 1;
    cudaLaunchKernelEx(&cfg, score_kernel,
                       queries, keys, Wa_b, Va_w, ctx_out, w_out);
}

// round 16
// speedup vs baseline: 1.0141x; 1.0141x over previous
#include <cuda_runtime.h>
#include <cuda_bf16.h>
#include <cuda_fp16.h>

#define H     128
#define BATCH 8
#define TQ    512
#define TK    512

// Device scratch (allocation-free rule: __device__ globals)
__device__ __align__(16) __half2 g_kph[BATCH * (H/2) * TK];  // [b][h/2][k] packed h-pairs
__device__ __align__(16) float   g_WaT[H * H];               // Wa transposed: WaT[k][h]

__device__ __forceinline__ __half2 tanh2(__half2 x) {
    unsigned xi = *(unsigned*)&x, yi;
    asm("tanh.approx.f16x2 %0, %1;" : "=r"(yi) : "r"(xi));
    return *(__half2*)&yi;
}

// ---------------------------------------------------------------------------
// Kernel 1: prep — EXACT round-13 form (best measured), + PDL trigger.
//   z==0: k-projection  g_kph[b][h/2][t] = keys @ Ua_w^T + Ua_b (half2 pairs)
//         128 threads, 16 accumulator chains per thread, unroll 4.
//   z==1: Wa transpose into g_WaT (b==0 blocks only)
// grid = (32, B, 2), block = 128
// ---------------------------------------------------------------------------
__global__ void __launch_bounds__(128) prep_kernel(
    const float* __restrict__ keys,
    const float* __restrict__ Ua_w, const float* __restrict__ Ua_b,
    const float* __restrict__ Wa_w)
{
#if __CUDA_ARCH__ >= 900
    cudaTriggerProgrammaticLaunchCompletion();   // let score launch early
#endif
    const int tile = blockIdx.x;   // 32 tiles of 16 rows
    const int b    = blockIdx.y;

    if (blockIdx.z == 1) {
        if (b != 0) return;
        const int r0 = tile * 4;
        #pragma unroll
        for (int i = threadIdx.x; i < 4 * H; i += 128) {
            int r = i >> 7, c = i & 127;
            g_WaT[(size_t)c * H + r0 + r] = Wa_w[(size_t)(r0 + r) * H + c];
        }
        return;
    }

    const int t0 = tile * 16;
    __shared__ __align__(16) float xs[16][H];
    __shared__ float sh[H][16];    // for h-pair packing

    const float4* xsrc = (const float4*)(keys + (size_t)(b * 512 + t0) * H);
    #pragma unroll
    for (int i = threadIdx.x; i < 16 * H / 4; i += 128)
        ((float4*)xs)[i] = xsrc[i];
    __syncthreads();

    const int h = threadIdx.x;
    float acc[16];
    const float bv = Ua_b[h];
    #pragma unroll
    for (int t = 0; t < 16; t++) acc[t] = bv;

    const float4* Wrow = (const float4*)(Ua_w + h * H);
    #pragma unroll 4
    for (int i = 0; i < H / 4; i++) {
        float4 w4 = Wrow[i];
        #pragma unroll
        for (int t = 0; t < 16; t++) {
            float4 xv = ((const float4*)xs[t])[i];
            acc[t] = fmaf(xv.x, w4.x, fmaf(xv.y, w4.y, fmaf(xv.z, w4.z, fmaf(xv.w, w4.w, acc[t]))));
        }
    }

    #pragma unroll
    for (int t = 0; t < 16; t++) sh[h][t] = acc[t];
    __syncthreads();
    __half2* dst = g_kph + (size_t)b * (H/2) * TK + t0;
    #pragma unroll
    for (int r = 0; r < 8; r++) {
        int idx = threadIdx.x + 128 * r;   // 0..1023
        int t   = idx & 15;
        int j   = idx >> 4;                // h-pair 0..63
        dst[(size_t)j * TK + t] = __floats2half2_rn(sh[2*j][t], sh[2*j+1][t]);
    }
}

// ---------------------------------------------------------------------------
// Kernel 2: FUSED q-projection + scores + softmax + context (PDL secondary).
// EXACT round-13 compute path; grid-sync after input-only qs staging and
// before any g_WaT/g_kph read. Early blocks hide launch gap + staging.
// grid (TQ/4, B), block 128 (4 warps, 1 q/warp).
// ---------------------------------------------------------------------------
__global__ void __launch_bounds__(128) score_kernel(
    const float* __restrict__ queries,
    const float* __restrict__ keys,
    const float* __restrict__ Wa_b,
    const float* __restrict__ Va_w,
    float* __restrict__ ctx_out,   // (B, TQ, H)
    float* __restrict__ w_out)     // (B, TQ, TK)
{
    __shared__ __align__(16) float  qs[4][H];    // 2 KB raw query rows
    __shared__ __align__(8)  float2 qm[4][H/2];  // 4 KB {q2 bits, va2 bits}
    __shared__ float wsm[4][TK];                 // 8 KB softmax weights

    const int b    = blockIdx.y;
    const int wid  = threadIdx.x >> 5;
    const int lane = threadIdx.x & 31;
    const int q    = blockIdx.x * 4 + wid;

    ((float4*)qs)[threadIdx.x] =
        ((const float4*)(queries + (size_t)(b * TQ + blockIdx.x * 4) * H))[threadIdx.x];
    __syncthreads();

#if __CUDA_ARCH__ >= 900
    cudaGridDependencySynchronize();   // prep done: g_WaT + g_kph visible
#endif

    // ---- Fused q-projection: qp[4lane..4lane+3] = q-row @ Wa^T + b ----
    float4 acc = ((const float4*)Wa_b)[lane];
    {
        const float*  qrow = qs[wid];
        const float4* WT   = (const float4*)g_WaT + lane;   // WaT[k][4lane..+3]
        #pragma unroll 8
        for (int k = 0; k < H; k++) {
            float  xk = qrow[k];        // broadcast LDS
            float4 wv = WT[k * 32];     // coalesced LDG.128, L1-hot
            acc.x = fmaf(xk, wv.x, acc.x);
            acc.y = fmaf(xk, wv.y, acc.y);
            acc.z = fmaf(xk, wv.z, acc.z);
            acc.w = fmaf(xk, wv.w, acc.w);
        }
    }
    {
        __half2 q2a = __floats2half2_rn(acc.x, acc.y);
        __half2 q2b = __floats2half2_rn(acc.z, acc.w);
        float4  vv  = ((const float4*)Va_w)[lane];
        __half2 va0 = __floats2half2_rn(vv.x, vv.y);
        __half2 va1 = __floats2half2_rn(vv.z, vv.w);
        qm[wid][2*lane]   = make_float2(__uint_as_float(*(unsigned*)&q2a),
                                        __uint_as_float(*(unsigned*)&va0));
        qm[wid][2*lane+1] = make_float2(__uint_as_float(*(unsigned*)&q2b),
                                        __uint_as_float(*(unsigned*)&va1));
    }
    __syncwarp();

    // ---- Score hot loop (MUFU floor): lane owns keys 64t + 2lane + e ----
    float a[16];
    #pragma unroll
    for (int i = 0; i < 16; i++) a[i] = 0.f;

    const uint2* kb2 = (const uint2*)(g_kph + (size_t)b * (H/2) * TK) + lane;

    #pragma unroll 1
    for (int jb = 0; jb < 8; jb++) {           // 8 blocks of 8 h-pairs
        __half2 acc2[16];
        #pragma unroll
        for (int i = 0; i < 16; i++) acc2[i] = __half2half2(__float2half(0.f));

        #pragma unroll
        for (int j2 = 0; j2 < 8; j2++) {
            int j = jb * 8 + j2;
            float2 meta = qm[wid][j];          // broadcast LDS.64
            unsigned qb2b = __float_as_uint(meta.x);
            unsigned vb2b = __float_as_uint(meta.y);
            __half2 q2  = *(__half2*)&qb2b;
            __half2 va2 = *(__half2*)&vb2b;

            const uint2* kr = kb2 + j * (TK / 2);
            uint2 kk[8];
            #pragma unroll
            for (int t = 0; t < 8; t++) kk[t] = kr[t * 32];   // MLP=8 LDG.64
            #pragma unroll
            for (int t = 0; t < 8; t++) {
                __half2 k0 = *(__half2*)&kk[t].x;
                __half2 k1 = *(__half2*)&kk[t].y;
                acc2[2*t]   = __hfma2(va2, tanh2(__hadd2(q2, k0)), acc2[2*t]);
                acc2[2*t+1] = __hfma2(va2, tanh2(__hadd2(q2, k1)), acc2[2*t+1]);
            }
        }
        #pragma unroll
        for (int i = 0; i < 16; i++) {
            float2 f = __half22float2(acc2[i]);
            a[i] += f.x + f.y;                 // fold even/odd-h partial sums
        }
    }

    // ---- softmax in registers ----
    float m = a[0];
    #pragma unroll
    for (int i = 1; i < 16; i++) m = fmaxf(m, a[i]);
    #pragma unroll
    for (int o = 16; o > 0; o >>= 1)
        m = fmaxf(m, __shfl_xor_sync(0xffffffffu, m, o));

    float s = 0.f;
    #pragma unroll
    for (int i = 0; i < 16; i++) { a[i] = __expf(a[i] - m); s += a[i]; }
    #pragma unroll
    for (int o = 16; o > 0; o >>= 1)
        s += __shfl_xor_sync(0xffffffffu, s, o);

    const float inv = __fdividef(1.f, s);
    float* wrow = w_out + (size_t)(b * TQ + q) * TK;
    #pragma unroll
    for (int t = 0; t < 8; t++) {
        float2 wp = make_float2(a[2*t] * inv, a[2*t+1] * inv);
        int off = 64 * t + 2 * lane;
        *(float2*)(wrow + off)      = wp;      // required output (coalesced STG.64)
        *(float2*)(&wsm[wid][off])  = wp;      // for fused ctx broadcast reads
    }
    __syncwarp();

    // ---- Fused context: ctx[q][h] = sum_k w[k] * keys[k][h] ----
    float4 cacc = make_float4(0.f, 0.f, 0.f, 0.f);
    const float4* kb = (const float4*)(keys + (size_t)b * TK * H) + lane;
    const float* w0 = wsm[wid];
    #pragma unroll 8
    for (int key = 0; key < TK; key++) {
        float4 kv = kb[key * (H / 4)];         // coalesced LDG.128, L2-hot
        float  wa = w0[key];                   // broadcast LDS
        cacc.x = fmaf(wa, kv.x, cacc.x);
        cacc.y = fmaf(wa, kv.y, cacc.y);
        cacc.z = fmaf(wa, kv.z, cacc.z);
        cacc.w = fmaf(wa, kv.w, cacc.w);
    }
    ((float4*)(ctx_out + (size_t)(b * TQ + q) * H))[lane] = cacc;
}

// ---------------------------------------------------------------------------
extern "C" void kernel_launch(void* const* d_in, const int* in_sizes, int n_in,
                              void* d_out, int out_size)
{
    const float* queries = (const float*)d_in[0];
    const float* keys    = (const float*)d_in[1];
    const float* Wa_w    = (const float*)d_in[2];
    const float* Wa_b    = (const float*)d_in[3];
    const float* Ua_w    = (const float*)d_in[4];
    const float* Ua_b    = (const float*)d_in[5];
    const float* Va_w    = (const float*)d_in[6];
    // Va bias (d_in[7]) cancels in softmax -> unused.

    float* ctx_out = (float*)d_out;                     // (B, TQ, H)
    float* w_out   = ctx_out + BATCH * TQ * H;          // (B, TQ, TK)

    // 1) prep: k-projection + Wa transpose (round-13 form), PDL primary.
    dim3 g1(32, BATCH, 2);
    prep_kernel<<<g1, 128>>>(keys, Ua_w, Ua_b, Wa_w);

    // 2) fused score kernel as PDL secondary: launches while prep runs;
    //    grid sync (after input-only staging) gates g_WaT/g_kph reads.
    cudaLaunchConfig_t cfg = {};
    cfg.gridDim  = dim3(TQ / 4, BATCH);
    cfg.blockDim = dim3(128);
    cfg.dynamicSmemBytes = 0;
    cfg.stream = 0;
    cudaLaunchAttribute attrs[1];
    attrs[0].id = cudaLaunchAttributeProgrammaticStreamSerialization;
    attrs[0].val.programmaticStreamSerializationAllowed = 1;
    cfg.attrs = attrs;
    cfg.numAttrs = 1;
    cudaLaunchKernelEx(&cfg, score_kernel,
                       queries, keys, Wa_b, Va_w, ctx_out, w_out);
}

// round 17
// speedup vs baseline: 1.1162x; 1.1006x over previous
#include <cuda_runtime.h>
#include <cuda_bf16.h>
#include <cuda_fp16.h>

#define H     128
#define BATCH 8
#define TQ    512
#define TK    512

// Device scratch (allocation-free rule: __device__ globals)
__device__ __align__(16) __half2 g_kph[BATCH * (H/2) * TK];  // [b][h/2][k] packed h-pairs
__device__ __align__(16) float   g_WaT[H * H];               // Wa transposed: WaT[k][h]

__device__ __forceinline__ __half2 tanh2(__half2 x) {
    unsigned xi = *(unsigned*)&x, yi;
    asm("tanh.approx.f16x2 %0, %1;" : "=r"(yi) : "r"(xi));
    return *(__half2*)&yi;
}

// ---------------------------------------------------------------------------
// Kernel 1: prep — EXACT round-13 form (best measured), plain launch (no PDL).
//   z==0: k-projection  g_kph[b][h/2][t] = keys @ Ua_w^T + Ua_b (half2 pairs)
//   z==1: Wa transpose into g_WaT (b==0 blocks only)
// grid = (32, B, 2), block = 128
// ---------------------------------------------------------------------------
__global__ void __launch_bounds__(128) prep_kernel(
    const float* __restrict__ keys,
    const float* __restrict__ Ua_w, const float* __restrict__ Ua_b,
    const float* __restrict__ Wa_w)
{
    const int tile = blockIdx.x;   // 32 tiles of 16 rows
    const int b    = blockIdx.y;

    if (blockIdx.z == 1) {
        if (b != 0) return;
        const int r0 = tile * 4;
        #pragma unroll
        for (int i = threadIdx.x; i < 4 * H; i += 128) {
            int r = i >> 7, c = i & 127;
            g_WaT[(size_t)c * H + r0 + r] = Wa_w[(size_t)(r0 + r) * H + c];
        }
        return;
    }

    const int t0 = tile * 16;
    __shared__ __align__(16) float xs[16][H];
    __shared__ float sh[H][16];    // for h-pair packing

    const float4* xsrc = (const float4*)(keys + (size_t)(b * 512 + t0) * H);
    #pragma unroll
    for (int i = threadIdx.x; i < 16 * H / 4; i += 128)
        ((float4*)xs)[i] = xsrc[i];
    __syncthreads();

    const int h = threadIdx.x;
    float acc[16];
    const float bv = Ua_b[h];
    #pragma unroll
    for (int t = 0; t < 16; t++) acc[t] = bv;

    const float4* Wrow = (const float4*)(Ua_w + h * H);
    #pragma unroll 4
    for (int i = 0; i < H / 4; i++) {
        float4 w4 = Wrow[i];
        #pragma unroll
        for (int t = 0; t < 16; t++) {
            float4 xv = ((const float4*)xs[t])[i];
            acc[t] = fmaf(xv.x, w4.x, fmaf(xv.y, w4.y, fmaf(xv.z, w4.z, fmaf(xv.w, w4.w, acc[t]))));
        }
    }

    #pragma unroll
    for (int t = 0; t < 16; t++) sh[h][t] = acc[t];
    __syncthreads();
    __half2* dst = g_kph + (size_t)b * (H/2) * TK + t0;
    #pragma unroll
    for (int r = 0; r < 8; r++) {
        int idx = threadIdx.x + 128 * r;   // 0..1023
        int t   = idx & 15;
        int j   = idx >> 4;                // h-pair 0..63
        dst[(size_t)j * TK + t] = __floats2half2_rn(sh[2*j][t], sh[2*j+1][t]);
    }
}

// ---------------------------------------------------------------------------
// Kernel 2: fused q-proj + scores + softmax + context, 2 WARPS PER QUERY.
// grid (TQ/2, B) = 2048 blocks, block 128 (4 warps = 2 queries x 2 key-halves).
// Warp (wpair, half): query q = 2*blockIdx.x + wpair, keys [256*half, +256).
// Doubles resident warps (occupancy was grid-limited at 1024 blocks).
// ---------------------------------------------------------------------------
__global__ void __launch_bounds__(128) score_kernel(
    const float* __restrict__ queries,
    const float* __restrict__ keys,
    const float* __restrict__ Wa_b,
    const float* __restrict__ Va_w,
    float* __restrict__ ctx_out,   // (B, TQ, H)
    float* __restrict__ w_out)     // (B, TQ, TK)
{
    __shared__ __align__(16) float  qs[2][H];      // 1 KB raw query rows
    __shared__ __align__(8)  float2 qm[2][H/2];    // 1 KB {q2 bits, va2 bits}
    __shared__ float wsm[2][TK];                   // 4 KB softmax weights
    __shared__ float redm[2][2], reds[2][2];       // cross-warp max/sum
    __shared__ __align__(16) float cpart[2][H];    // 1 KB ctx partials (half=1)

    const int b     = blockIdx.y;
    const int wid   = threadIdx.x >> 5;
    const int lane  = threadIdx.x & 31;
    const int wpair = wid >> 1;     // query within block
    const int half  = wid & 1;      // key half
    const int q     = blockIdx.x * 2 + wpair;

    // Stage 2 query rows (64 float4)
    if (threadIdx.x < 64)
        ((float4*)qs)[threadIdx.x] =
            ((const float4*)(queries + (size_t)(b * TQ + blockIdx.x * 2) * H))[threadIdx.x];
    __syncthreads();

    // ---- q-projection (half==0 warp of each pair), packed into qm ----
    if (half == 0) {
        float4 acc = ((const float4*)Wa_b)[lane];
        const float*  qrow = qs[wpair];
        const float4* WT   = (const float4*)g_WaT + lane;   // WaT[k][4lane..+3]
        #pragma unroll 8
        for (int k = 0; k < H; k++) {
            float  xk = qrow[k];        // broadcast LDS
            float4 wv = WT[k * 32];     // coalesced LDG.128, L1-hot
            acc.x = fmaf(xk, wv.x, acc.x);
            acc.y = fmaf(xk, wv.y, acc.y);
            acc.z = fmaf(xk, wv.z, acc.z);
            acc.w = fmaf(xk, wv.w, acc.w);
        }
        __half2 q2a = __floats2half2_rn(acc.x, acc.y);
        __half2 q2b = __floats2half2_rn(acc.z, acc.w);
        float4  vv  = ((const float4*)Va_w)[lane];
        __half2 va0 = __floats2half2_rn(vv.x, vv.y);
        __half2 va1 = __floats2half2_rn(vv.z, vv.w);
        qm[wpair][2*lane]   = make_float2(__uint_as_float(*(unsigned*)&q2a),
                                          __uint_as_float(*(unsigned*)&va0));
        qm[wpair][2*lane+1] = make_float2(__uint_as_float(*(unsigned*)&q2b),
                                          __uint_as_float(*(unsigned*)&va1));
    }
    __syncthreads();

    // ---- Score hot loop: 256 keys/warp, key = 256*half + 64t + 2lane + e ----
    float a[8];
    #pragma unroll
    for (int i = 0; i < 8; i++) a[i] = 0.f;

    const uint2* kb2 = (const uint2*)(g_kph + (size_t)b * (H/2) * TK)
                       + 128 * half + lane;

    #pragma unroll 1
    for (int jb = 0; jb < 8; jb++) {           // 8 blocks of 8 h-pairs
        __half2 acc2[8];
        #pragma unroll
        for (int i = 0; i < 8; i++) acc2[i] = __half2half2(__float2half(0.f));

        #pragma unroll
        for (int j2 = 0; j2 < 8; j2++) {
            int j = jb * 8 + j2;
            float2 meta = qm[wpair][j];        // broadcast LDS.64
            unsigned qb2b = __float_as_uint(meta.x);
            unsigned vb2b = __float_as_uint(meta.y);
            __half2 q2  = *(__half2*)&qb2b;
            __half2 va2 = *(__half2*)&vb2b;

            const uint2* kr = kb2 + j * (TK / 2);
            uint2 kk[4];
            #pragma unroll
            for (int t = 0; t < 4; t++) kk[t] = kr[t * 32];   // MLP=4 LDG.64
            #pragma unroll
            for (int t = 0; t < 4; t++) {
                __half2 k0 = *(__half2*)&kk[t].x;
                __half2 k1 = *(__half2*)&kk[t].y;
                acc2[2*t]   = __hfma2(va2, tanh2(__hadd2(q2, k0)), acc2[2*t]);
                acc2[2*t+1] = __hfma2(va2, tanh2(__hadd2(q2, k1)), acc2[2*t+1]);
            }
        }
        #pragma unroll
        for (int i = 0; i < 8; i++) {
            float2 f = __half22float2(acc2[i]);
            a[i] += f.x + f.y;                 // fold even/odd-h partial sums
        }
    }

    // ---- softmax across the warp pair ----
    float m = a[0];
    #pragma unroll
    for (int i = 1; i < 8; i++) m = fmaxf(m, a[i]);
    #pragma unroll
    for (int o = 16; o > 0; o >>= 1)
        m = fmaxf(m, __shfl_xor_sync(0xffffffffu, m, o));
    if (lane == 0) redm[wpair][half] = m;
    __syncthreads();
    m = fmaxf(redm[wpair][0], redm[wpair][1]);

    float s = 0.f;
    #pragma unroll
    for (int i = 0; i < 8; i++) { a[i] = __expf(a[i] - m); s += a[i]; }
    #pragma unroll
    for (int o = 16; o > 0; o >>= 1)
        s += __shfl_xor_sync(0xffffffffu, s, o);
    if (lane == 0) reds[wpair][half] = s;
    __syncthreads();
    s = reds[wpair][0] + reds[wpair][1];

    const float inv = __fdividef(1.f, s);
    float* wrow = w_out + (size_t)(b * TQ + q) * TK + 256 * half;
    float* wsh  = &wsm[wpair][256 * half];
    #pragma unroll
    for (int t = 0; t < 4; t++) {
        float2 wp = make_float2(a[2*t] * inv, a[2*t+1] * inv);
        int off = 64 * t + 2 * lane;
        *(float2*)(wrow + off) = wp;           // required output (coalesced)
        *(float2*)(wsh  + off) = wp;           // own-segment smem (own-warp read)
    }
    __syncwarp();

    // ---- Fused context: partial over own 256 keys, combine across pair ----
    float4 cacc = make_float4(0.f, 0.f, 0.f, 0.f);
    const float4* kb = (const float4*)(keys + (size_t)(b * TK + 256 * half) * H) + lane;
    const float* w0 = wsh;
    #pragma unroll 8
    for (int key = 0; key < 256; key++) {
        float4 kv = kb[key * (H / 4)];         // coalesced LDG.128, L2-hot
        float  wa = w0[key];                   // broadcast LDS (own segment)
        cacc.x = fmaf(wa, kv.x, cacc.x);
        cacc.y = fmaf(wa, kv.y, cacc.y);
        cacc.z = fmaf(wa, kv.z, cacc.z);
        cacc.w = fmaf(wa, kv.w, cacc.w);
    }
    if (half == 1)
        ((float4*)cpart[wpair])[lane] = cacc;
    __syncthreads();
    if (half == 0) {
        float4 o4 = ((float4*)cpart[wpair])[lane];
        cacc.x += o4.x; cacc.y += o4.y; cacc.z += o4.z; cacc.w += o4.w;
        ((float4*)(ctx_out + (size_t)(b * TQ + q) * H))[lane] = cacc;
    }
}

// ---------------------------------------------------------------------------
extern "C" void kernel_launch(void* const* d_in, const int* in_sizes, int n_in,
                              void* d_out, int out_size)
{
    const float* queries = (const float*)d_in[0];
    const float* keys    = (const float*)d_in[1];
    const float* Wa_w    = (const float*)d_in[2];
    const float* Wa_b    = (const float*)d_in[3];
    const float* Ua_w    = (const float*)d_in[4];
    const float* Ua_b    = (const float*)d_in[5];
    const float* Va_w    = (const float*)d_in[6];
    // Va bias (d_in[7]) cancels in softmax -> unused.

    float* ctx_out = (float*)d_out;                     // (B, TQ, H)
    float* w_out   = ctx_out + BATCH * TQ * H;          // (B, TQ, TK)

    dim3 g1(32, BATCH, 2);
    prep_kernel<<<g1, 128>>>(keys, Ua_w, Ua_b, Wa_w);

    dim3 g2(TQ / 2, BATCH);
    score_kernel<<<g2, 128>>>(queries, keys, Wa_b, Va_w, ctx_out, w_out);
}